// round 3
// baseline (speedup 1.0000x reference)
#include <cuda_runtime.h>
#include <math.h>

#define NV      12288
#define NFEAT   128
#define NHID    64
#define NCLASS  16
#define MAXDEG  128

#define XW1_ROWS   16
#define XW1_BLOCKS (NV / XW1_ROWS)   // 768

// ---------------- device scratch (allocation-free) ----------------
__device__ int   g_cols[(size_t)NV * MAXDEG];   // neighbor col indices per row
__device__ int   g_cnt [NV];                    // neighbor count (excl. self)
__device__ float g_dinv[NV];                    // (deg+1)^-1/2
__device__ float g_Y1  [(size_t)NV * NHID];     // x @ W1 (UNSCALED)
__device__ float g_Z2  [(size_t)NV * NCLASS];   // d * (H1 @ W2)

// =================================================================
// K1: heterogeneous grid.
//   blocks [0, NV)          : extract row -> cols/cnt/dinv  (DRAM-bound)
//   blocks [NV, NV+768)     : Y1 = x @ W1 tile (16 rows)    (FMA-bound)
// =================================================================
union SmemK1 {
    struct { float W[NFEAT * NHID]; float x[XW1_ROWS][NFEAT]; } xw; // 40KB
    int cnt;
};

__global__ void __launch_bounds__(256) k1_extract_xw1(const float* __restrict__ adj,
                                                      const float* __restrict__ x,
                                                      const float* __restrict__ W1) {
    __shared__ SmemK1 sm;

    if (blockIdx.x < NV) {
        // ---------- extract path ----------
        const int row = blockIdx.x;
        if (threadIdx.x == 0) sm.cnt = 0;
        __syncthreads();

        const uint4* rp = reinterpret_cast<const uint4*>(adj + (size_t)row * NV);
        // 12288 floats / 4 = 3072 uint4; 256 threads -> 12 per thread.
        uint4 v[12];
        #pragma unroll
        for (int it = 0; it < 12; it++)
            v[it] = rp[threadIdx.x + it * 256];       // 12 LDG.128 in flight (MLP=12)

        int* mycols = g_cols + (size_t)row * MAXDEG;
        #pragma unroll
        for (int it = 0; it < 12; it++) {
            unsigned m = (v[it].x | v[it].y) | (v[it].z | v[it].w);
            if (m) {                                   // rare (~0.8% of chunks)
                int base = (threadIdx.x + it * 256) << 2;
                if (v[it].x) { int p = atomicAdd(&sm.cnt, 1); if (p < MAXDEG) mycols[p] = base + 0; }
                if (v[it].y) { int p = atomicAdd(&sm.cnt, 1); if (p < MAXDEG) mycols[p] = base + 1; }
                if (v[it].z) { int p = atomicAdd(&sm.cnt, 1); if (p < MAXDEG) mycols[p] = base + 2; }
                if (v[it].w) { int p = atomicAdd(&sm.cnt, 1); if (p < MAXDEG) mycols[p] = base + 3; }
            }
        }
        __syncthreads();
        if (threadIdx.x == 0) {
            int c = sm.cnt;
            g_cnt[row]  = (c < MAXDEG) ? c : MAXDEG;
            g_dinv[row] = rsqrtf((float)c + 1.0f);    // +1 = self loop
        }
    } else {
        // ---------- x @ W1 path (16 rows per block, unscaled) ----------
        const int row0 = (blockIdx.x - NV) * XW1_ROWS;
        // stage W1 (vectorized: 2048 float4)
        {
            const float4* Wv = reinterpret_cast<const float4*>(W1);
            float4* sWv = reinterpret_cast<float4*>(sm.xw.W);
            #pragma unroll
            for (int i = 0; i < (NFEAT * NHID / 4) / 256; i++)
                sWv[threadIdx.x + i * 256] = Wv[threadIdx.x + i * 256];
        }
        // stage 16 rows of x (512 float4)
        {
            const float4* xv = reinterpret_cast<const float4*>(x + (size_t)row0 * NFEAT);
            float4* sxv = reinterpret_cast<float4*>(&sm.xw.x[0][0]);
            #pragma unroll
            for (int i = 0; i < (XW1_ROWS * NFEAT / 4) / 256; i++)
                sxv[threadIdx.x + i * 256] = xv[threadIdx.x + i * 256];
        }
        __syncthreads();

        const int k  = threadIdx.x & 63;      // hidden col
        const int rl = threadIdx.x >> 6;      // 0..3
        #pragma unroll
        for (int g = 0; g < 4; g++) {
            const int r = g * 4 + rl;
            float acc = 0.0f;
            #pragma unroll
            for (int f = 0; f < NFEAT; f++)
                acc = fmaf(sm.xw.x[r][f], sm.xw.W[f * NHID + k], acc);
            g_Y1[(size_t)(row0 + r) * NHID + k] = acc;   // unscaled
        }
    }
}

// =================================================================
// K2: gather layer 1 (with deferred d_j scaling) + relu + fused @W2
//     -> g_Z2[row] = d_row * (H1[row] @ W2)      (H1 stays in SMEM)
// block: 256 threads = 4 rows x 64 feats
// =================================================================
__global__ void __launch_bounds__(256) k2_spmm1_hw2(const float* __restrict__ W2) {
    __shared__ float sW2[NHID * NCLASS];      // 4KB
    __shared__ float sh[4][NHID];             // H1 rows
    __shared__ float sp[4][4][NCLASS];        // partials

    for (int i = threadIdx.x; i < NHID * NCLASS; i += 256) sW2[i] = W2[i];

    const int r   = threadIdx.x >> 6;         // 0..3
    const int k   = threadIdx.x & 63;
    const int row = blockIdx.x * 4 + r;
    const int cnt = g_cnt[row];
    const int* cols = g_cols + (size_t)row * MAXDEG;
    const float di = g_dinv[row];

    float acc = di * g_Y1[(size_t)row * NHID + k];     // self-loop term
    for (int e = 0; e < cnt; e++) {
        int j = cols[e];
        acc = fmaf(g_dinv[j], g_Y1[(size_t)j * NHID + k], acc);
    }
    sh[r][k] = fmaxf(acc * di, 0.0f);                  // H1[row][k]
    __syncthreads();

    // H1[row] @ W2 : 64 threads/row -> 16 classes x 4 partials of 16 feats
    const int c = threadIdx.x & 15;
    const int p = (threadIdx.x >> 4) & 3;
    float part = 0.0f;
    #pragma unroll
    for (int f = 0; f < 16; f++)
        part = fmaf(sh[r][p * 16 + f], sW2[(p * 16 + f) * NCLASS + c], part);
    sp[r][p][c] = part;
    __syncthreads();

    if (p == 0) {
        float val = ((sp[r][0][c] + sp[r][1][c]) + (sp[r][2][c] + sp[r][3][c]));
        g_Z2[(size_t)row * NCLASS + c] = val * di;     // = d_row * (H1 W2)_row
    }
}

// =================================================================
// K3: gather layer 2 + relu + log_softmax -> out
// block: 128 threads = 8 rows x 16 classes
// =================================================================
__global__ void __launch_bounds__(128) k3_spmm2_out(float* __restrict__ out) {
    const int row = blockIdx.x * 8 + (threadIdx.x >> 4);
    const int c   = threadIdx.x & 15;
    const int cnt = g_cnt[row];
    const int* cols = g_cols + (size_t)row * MAXDEG;

    float acc = g_Z2[(size_t)row * NCLASS + c];        // self (already d_j-scaled)
    for (int e = 0; e < cnt; e++)
        acc += g_Z2[(size_t)cols[e] * NCLASS + c];
    float h = fmaxf(acc * g_dinv[row], 0.0f);

    // log_softmax over the 16-lane group (xor offsets stay in-group)
    float m = h;
    #pragma unroll
    for (int o = 8; o >= 1; o >>= 1)
        m = fmaxf(m, __shfl_xor_sync(0xffffffffu, m, o));
    float ex = expf(h - m);
    float s = ex;
    #pragma unroll
    for (int o = 8; o >= 1; o >>= 1)
        s += __shfl_xor_sync(0xffffffffu, s, o);
    out[(size_t)row * NCLASS + c] = (h - m) - logf(s);
}

// ---------------- launch ----------------
extern "C" void kernel_launch(void* const* d_in, const int* in_sizes, int n_in,
                              void* d_out, int out_size) {
    const float *x = nullptr, *adj = nullptr, *W1 = nullptr, *W2 = nullptr;
    for (int i = 0; i < n_in; i++) {
        long s = (long)in_sizes[i];
        if      (s == (long)NV * NV)       adj = (const float*)d_in[i];
        else if (s == (long)NV * NFEAT)    x   = (const float*)d_in[i];
        else if (s == (long)NFEAT * NHID)  W1  = (const float*)d_in[i];
        else if (s == (long)NHID * NCLASS) W2  = (const float*)d_in[i];
    }
    float* out = (float*)d_out;

    k1_extract_xw1<<<NV + XW1_BLOCKS, 256>>>(adj, x, W1);
    k2_spmm1_hw2  <<<NV / 4,          256>>>(W2);
    k3_spmm2_out  <<<NV / 8,          128>>>(out);
}

// round 4
// speedup vs baseline: 1.4118x; 1.4118x over previous
#include <cuda_runtime.h>
#include <math.h>

#define NV      12288
#define NFEAT   128
#define NHID    64
#define NCLASS  16
#define MAXDEG  128

#define EX_U       8
#define EX_T       256
#define NCHUNKS    ((size_t)NV * NV / 4)                 // 37,748,736 uint4
#define EX_BLOCKS  (NCHUNKS / (EX_U * EX_T))             // 18,432 (exact)

#define XW1_ROWS   16
#define XW1_BLOCKS (NV / XW1_ROWS)                       // 768

// ---------------- device scratch (allocation-free) ----------------
__device__ int   g_cnt [NV];                    // true neighbor count (excl. self)
__device__ int   g_cols[(size_t)NV * MAXDEG];   // neighbor col indices per row
__device__ float g_dinv[NV];                    // (deg+1)^-1/2
__device__ float g_Z1  [(size_t)NV * NHID];     // d ⊙ (x @ W1)  (pre-scaled)
__device__ float g_Z2  [(size_t)NV * NCLASS];   // d ⊙ (H1 @ W2) (pre-scaled)

// ---------------- K0: zero the counters (graph replays need this) --------
__global__ void k0_zero() {
    int i = blockIdx.x * blockDim.x + threadIdx.x;
    if (i < NV) g_cnt[i] = 0;
}

// =================================================================
// K1: flat streaming extract. Grid-stride-free exact mapping:
//   block b covers chunks [b*2048, (b+1)*2048); thread batches 8 LDG.128.
//   Low regs, no smem -> high occupancy -> DRAM-saturating MLP.
// =================================================================
__global__ void __launch_bounds__(EX_T) k1_extract(const uint4* __restrict__ adj) {
    const unsigned base = blockIdx.x * (EX_U * EX_T) + threadIdx.x;

    uint4 v[EX_U];
    #pragma unroll
    for (int u = 0; u < EX_U; u++)
        v[u] = adj[(size_t)base + u * EX_T];            // 8 LDG.128 in flight

    #pragma unroll
    for (int u = 0; u < EX_U; u++) {
        unsigned m = (v[u].x | v[u].y) | (v[u].z | v[u].w);
        if (m) {                                        // ~0.8% of chunks
            unsigned idx4 = base + u * EX_T;            // uint4 index
            unsigned row  = idx4 / (NV / 4);            // = elem/NV
            unsigned col0 = (idx4 - row * (NV / 4)) << 2;
            int* mycols = g_cols + (size_t)row * MAXDEG;
            if (v[u].x) { int p = atomicAdd(&g_cnt[row], 1); if (p < MAXDEG) mycols[p] = col0 + 0; }
            if (v[u].y) { int p = atomicAdd(&g_cnt[row], 1); if (p < MAXDEG) mycols[p] = col0 + 1; }
            if (v[u].z) { int p = atomicAdd(&g_cnt[row], 1); if (p < MAXDEG) mycols[p] = col0 + 2; }
            if (v[u].w) { int p = atomicAdd(&g_cnt[row], 1); if (p < MAXDEG) mycols[p] = col0 + 3; }
        }
    }
}

// =================================================================
// K2: Z1 = dinv ⊙ (x @ W1), and materialize g_dinv.
// 768 blocks x 256 threads; 16 rows/block; W1+x staged in smem.
// =================================================================
__global__ void __launch_bounds__(256) k2_xw1(const float* __restrict__ x,
                                              const float* __restrict__ W1) {
    __shared__ float sW[NFEAT * NHID];       // 32 KB
    __shared__ float sx[XW1_ROWS][NFEAT];    // 8 KB
    const int row0 = blockIdx.x * XW1_ROWS;

    {   // stage W1 (2048 float4)
        const float4* Wv = reinterpret_cast<const float4*>(W1);
        float4* sWv = reinterpret_cast<float4*>(sW);
        #pragma unroll
        for (int i = 0; i < (NFEAT * NHID / 4) / 256; i++)
            sWv[threadIdx.x + i * 256] = Wv[threadIdx.x + i * 256];
    }
    {   // stage 16 rows of x (512 float4)
        const float4* xv = reinterpret_cast<const float4*>(x + (size_t)row0 * NFEAT);
        float4* sxv = reinterpret_cast<float4*>(&sx[0][0]);
        #pragma unroll
        for (int i = 0; i < (XW1_ROWS * NFEAT / 4) / 256; i++)
            sxv[threadIdx.x + i * 256] = xv[threadIdx.x + i * 256];
    }
    __syncthreads();

    const int k  = threadIdx.x & 63;
    const int rl = threadIdx.x >> 6;                    // 0..3
    #pragma unroll
    for (int g = 0; g < 4; g++) {
        const int r   = g * 4 + rl;
        const int row = row0 + r;
        const float di = rsqrtf((float)g_cnt[row] + 1.0f);
        if (k == 0) g_dinv[row] = di;
        float acc = 0.0f;
        #pragma unroll
        for (int f = 0; f < NFEAT; f++)
            acc = fmaf(sx[r][f], sW[f * NHID + k], acc);
        g_Z1[(size_t)row * NHID + k] = acc * di;        // pre-scaled
    }
}

// =================================================================
// K3: gather layer 1 + relu, fused @W2 -> g_Z2 = d ⊙ (H1 @ W2).
// 4 rows x 64 feats per block. Gather unrolled x4 (batched L2 loads).
// =================================================================
__global__ void __launch_bounds__(256) k3_spmm1_hw2(const float* __restrict__ W2) {
    __shared__ float sW2[NHID * NCLASS];     // 4 KB
    __shared__ float sh[4][NHID];
    __shared__ float sp[4][4][NCLASS];

    for (int i = threadIdx.x; i < NHID * NCLASS; i += 256) sW2[i] = W2[i];

    const int r   = threadIdx.x >> 6;
    const int k   = threadIdx.x & 63;
    const int row = blockIdx.x * 4 + r;
    int cnt = g_cnt[row]; if (cnt > MAXDEG) cnt = MAXDEG;
    const int* cols = g_cols + (size_t)row * MAXDEG;
    const float di = g_dinv[row];

    float acc = g_Z1[(size_t)row * NHID + k];           // self loop (Z1 = d⊙Y1)
    int e = 0;
    for (; e + 4 <= cnt; e += 4) {
        int j0 = cols[e], j1 = cols[e + 1], j2 = cols[e + 2], j3 = cols[e + 3];
        float a0 = g_Z1[(size_t)j0 * NHID + k];
        float a1 = g_Z1[(size_t)j1 * NHID + k];
        float a2 = g_Z1[(size_t)j2 * NHID + k];
        float a3 = g_Z1[(size_t)j3 * NHID + k];
        acc += (a0 + a1) + (a2 + a3);
    }
    for (; e < cnt; e++)
        acc += g_Z1[(size_t)cols[e] * NHID + k];
    sh[r][k] = fmaxf(acc * di, 0.0f);                   // H1[row][k]
    __syncthreads();

    // H1[row] @ W2 : 16 classes x 4 partials of 16 feats
    const int c = threadIdx.x & 15;
    const int p = (threadIdx.x >> 4) & 3;
    float part = 0.0f;
    #pragma unroll
    for (int f = 0; f < 16; f++)
        part = fmaf(sh[r][p * 16 + f], sW2[(p * 16 + f) * NCLASS + c], part);
    sp[r][p][c] = part;
    __syncthreads();

    if (p == 0) {
        float val = (sp[r][0][c] + sp[r][1][c]) + (sp[r][2][c] + sp[r][3][c]);
        g_Z2[(size_t)row * NCLASS + c] = val * di;      // pre-scaled
    }
}

// =================================================================
// K4: gather layer 2 + relu + log_softmax -> out
// 8 rows x 16 classes per block; gather unrolled x4.
// =================================================================
__global__ void __launch_bounds__(128) k4_spmm2_out(float* __restrict__ out) {
    const int row = blockIdx.x * 8 + (threadIdx.x >> 4);
    const int c   = threadIdx.x & 15;
    int cnt = g_cnt[row]; if (cnt > MAXDEG) cnt = MAXDEG;
    const int* cols = g_cols + (size_t)row * MAXDEG;

    float acc = g_Z2[(size_t)row * NCLASS + c];
    int e = 0;
    for (; e + 4 <= cnt; e += 4) {
        int j0 = cols[e], j1 = cols[e + 1], j2 = cols[e + 2], j3 = cols[e + 3];
        float a0 = g_Z2[(size_t)j0 * NCLASS + c];
        float a1 = g_Z2[(size_t)j1 * NCLASS + c];
        float a2 = g_Z2[(size_t)j2 * NCLASS + c];
        float a3 = g_Z2[(size_t)j3 * NCLASS + c];
        acc += (a0 + a1) + (a2 + a3);
    }
    for (; e < cnt; e++)
        acc += g_Z2[(size_t)cols[e] * NCLASS + c];
    float h = fmaxf(acc * g_dinv[row], 0.0f);

    float m = h;
    #pragma unroll
    for (int o = 8; o >= 1; o >>= 1)
        m = fmaxf(m, __shfl_xor_sync(0xffffffffu, m, o));
    float ex = expf(h - m);
    float s = ex;
    #pragma unroll
    for (int o = 8; o >= 1; o >>= 1)
        s += __shfl_xor_sync(0xffffffffu, s, o);
    out[(size_t)row * NCLASS + c] = (h - m) - logf(s);
}

// ---------------- launch ----------------
extern "C" void kernel_launch(void* const* d_in, const int* in_sizes, int n_in,
                              void* d_out, int out_size) {
    const float *x = nullptr, *adj = nullptr, *W1 = nullptr, *W2 = nullptr;
    for (int i = 0; i < n_in; i++) {
        long s = (long)in_sizes[i];
        if      (s == (long)NV * NV)       adj = (const float*)d_in[i];
        else if (s == (long)NV * NFEAT)    x   = (const float*)d_in[i];
        else if (s == (long)NFEAT * NHID)  W1  = (const float*)d_in[i];
        else if (s == (long)NHID * NCLASS) W2  = (const float*)d_in[i];
    }
    float* out = (float*)d_out;

    k0_zero      <<<(NV + 1023) / 1024, 1024>>>();
    k1_extract   <<<EX_BLOCKS, EX_T>>>((const uint4*)adj);
    k2_xw1       <<<XW1_BLOCKS, 256>>>(x, W1);
    k3_spmm1_hw2 <<<NV / 4,     256>>>(W2);
    k4_spmm2_out <<<NV / 8,     128>>>(out);
}